// round 9
// baseline (speedup 1.0000x reference)
#include <cuda_runtime.h>

#define TW 32
#define TH 64
#define IH 74          // TH + 10
#define HS 36          // map-pair stride in ull (float2) units; 288B rows
#define HMAP (IH*HS)   // ulls per map-pair
#define NBLOCKS (16*8*96)
#define SSIM_C1 (0.01f*0.01f)
#define SSIM_C2 (0.03f*0.03f)

typedef unsigned long long ull;

__device__ double g_accum = 0.0;
__device__ unsigned int g_count = 0u;

// Gaussian(sigma=1.5, ws=11) 1-D half-weights (symmetric), normalized.
#define W0 0.00102838f
#define W1 0.00759880f
#define W2 0.03600077f
#define W3 0.10936069f
#define W4 0.21300553f
#define W5 0.26601172f

#define FMA2(acc, a, b) asm("fma.rn.f32x2 %0, %1, %2, %0;" : "+l"(acc) : "l"(a), "l"(b))
#define SQ2(x)          asm("mul.rn.f32x2 %0, %0, %0;"     : "+l"(x))
#define PACK2(dst, lo, hi) asm("mov.b64 %0, {%1, %2};" : "=l"(dst) : "f"(lo), "f"(hi))

__global__ __launch_bounds__(256, 4) void ssim_main(
    const float* __restrict__ img1, const float* __restrict__ img2,
    float* __restrict__ out)
{
    extern __shared__ ull smem[];
    ull* hSD = smem;           // HMAP: h-blur of packed {S=a+b, D=a-b}
    ull* hPQ = hSD + HMAP;     // HMAP: h-blur of packed {S^2, D^2}
    __shared__ float red[8];

    // Packed {w,w} weights, 6 distinct by symmetry
    const float gwf[6] = {W0,W1,W2,W3,W4,W5};
    ull w2[6];
#pragma unroll
    for (int t = 0; t < 6; ++t)
        w2[t] = (ull)__float_as_uint(gwf[t]) * 0x100000001ull;

    const int tid = threadIdx.x;
    const int bx = blockIdx.x;
    const int p  = blockIdx.z;
    const float* p1 = img1 + (size_t)p * (512*512);
    const float* p2 = img2 + (size_t)p * (512*512);
    const int y0 = blockIdx.y * TH - 5;

    // ---- Stage A: 8-col items; fused aligned gmem load + horizontal conv ----
    // Item outputs: gmem cols 32bx+cb+c (c=0..7); window cols [32bx+cb-5, 32bx+cb+12].
    // Load 24 cols from LB = 32bx+cb-8 (16B-aligned): 6 x LDG.128 per image.
    for (int item = tid; item < IH*4; item += 256) {
        const int r  = item >> 2;
        const int cb = (item & 3) << 3;
        const int gy = y0 + r;
        const int LB = (bx << 5) + cb - 8;
        const bool rowok = (unsigned)gy < 512u;

        ull sd[18];
        ull acc[8] = {0,0,0,0,0,0,0,0};

        if (rowok) {
            if (LB >= 0 && LB <= 488) {
                const float4* qa = (const float4*)(p1 + (gy << 9) + LB);
                const float4* qb = (const float4*)(p2 + (gy << 9) + LB);
#pragma unroll
                for (int j = 0; j < 6; ++j) {
                    const float4 va = __ldg(qa + j);
                    const float4 vb = __ldg(qb + j);
                    const float a4[4] = {va.x, va.y, va.z, va.w};
                    const float b4[4] = {vb.x, vb.y, vb.z, vb.w};
#pragma unroll
                    for (int k = 0; k < 4; ++k) {
                        const int m = 4*j + k;          // loaded col offset
                        if (m >= 3 && m <= 20)          // window = loaded [3..20]
                            PACK2(sd[m-3], a4[k] + b4[k], a4[k] - b4[k]);
                    }
                }
            } else {
#pragma unroll
                for (int i = 0; i < 18; ++i) {
                    const int gx = LB + 3 + i;
                    const bool in = (unsigned)gx < 512u;
                    float a = in ? __ldg(p1 + (gy << 9) + gx) : 0.f;
                    float b = in ? __ldg(p2 + (gy << 9) + gx) : 0.f;
                    PACK2(sd[i], a + b, a - b);
                }
            }
            // SD half-pass: 8 outputs
#pragma unroll
            for (int t = 0; t < 11; ++t) {
                const ull w = w2[t < 6 ? t : 10 - t];
#pragma unroll
                for (int c = 0; c < 8; ++c) FMA2(acc[c], sd[c+t], w);
            }
        }
        {
            ulonglong2* oSD = (ulonglong2*)(hSD + r*HS + cb);
            oSD[0] = make_ulonglong2(acc[0], acc[1]);
            oSD[1] = make_ulonglong2(acc[2], acc[3]);
            oSD[2] = make_ulonglong2(acc[4], acc[5]);
            oSD[3] = make_ulonglong2(acc[6], acc[7]);
        }
        // PQ half-pass: square window in place, reaccumulate
#pragma unroll
        for (int c = 0; c < 8; ++c) acc[c] = 0ull;
        if (rowok) {
#pragma unroll
            for (int i = 0; i < 18; ++i) SQ2(sd[i]);
#pragma unroll
            for (int t = 0; t < 11; ++t) {
                const ull w = w2[t < 6 ? t : 10 - t];
#pragma unroll
                for (int c = 0; c < 8; ++c) FMA2(acc[c], sd[c+t], w);
            }
        }
        {
            ulonglong2* oPQ = (ulonglong2*)(hPQ + r*HS + cb);
            oPQ[0] = make_ulonglong2(acc[0], acc[1]);
            oPQ[1] = make_ulonglong2(acc[2], acc[3]);
            oPQ[2] = make_ulonglong2(acc[4], acc[5]);
            oPQ[3] = make_ulonglong2(acc[6], acc[7]);
        }
    }
    __syncthreads();

    // ---- Stage B: vertical conv (packed, sliding window) + SSIM, 8 rows/thread ----
    const int tx = tid & 31;
    const int tg = tid >> 5;
    const int r0 = tg << 3;

    ull accSD[8], accPQ[8];
#pragma unroll
    for (int rr = 0; rr < 8; ++rr) { accSD[rr] = 0ull; accPQ[rr] = 0ull; }

    const ull* bSD = hSD + tx;
    const ull* bPQ = hPQ + tx;
#pragma unroll
    for (int i = 0; i < 18; ++i) {
        const ull v1 = bSD[(r0+i)*HS];
        const ull v2 = bPQ[(r0+i)*HS];
#pragma unroll
        for (int rr = 0; rr < 8; ++rr) {
            const int t = i - rr;
            if (t >= 0 && t < 11) {
                const ull w = w2[t < 6 ? t : 10 - t];
                FMA2(accSD[rr], v1, w);
                FMA2(accPQ[rr], v2, w);
            }
        }
    }

    float local = 0.f;
#pragma unroll
    for (int rr = 0; rr < 8; ++rr) {
        const float2 sd = *(const float2*)&accSD[rr];
        const float2 pq = *(const float2*)&accPQ[rr];
        const float S = sd.x, D = sd.y, P = pq.x, Q = pq.y;
        const float S2h = 0.5f*(S*S), D2h = 0.5f*(D*D);
        const float u  = S2h - D2h;     // 2*mu1*mu2
        const float v  = S2h + D2h;     // mu1^2 + mu2^2
        const float pm = 0.5f*(P - Q);  // 2*E[xy]
        const float qm = 0.5f*(P + Q);  // E[x^2] + E[y^2]
        const float num = (u + SSIM_C1) * (pm - u + SSIM_C2);
        const float den = (v + SSIM_C1) * (qm - v + SSIM_C2);
        local += __fdividef(num, den);
    }

    // ---- Reduce: warp -> block -> global, last block finalizes ----
#pragma unroll
    for (int o = 16; o; o >>= 1)
        local += __shfl_xor_sync(0xffffffffu, local, o);
    if (tx == 0) red[tg] = local;
    __syncthreads();
    if (tid == 0) {
        float s = 0.f;
#pragma unroll
        for (int i = 0; i < 8; ++i) s += red[i];
        atomicAdd(&g_accum, (double)s);
        __threadfence();
        unsigned int v = atomicAdd(&g_count, 1u);
        if (v == NBLOCKS - 1u) {
            double tot = atomicAdd(&g_accum, 0.0);
            out[0] = (float)(tot * (1.0 / (96.0 * 512.0 * 512.0)));
            g_accum = 0.0;
            __threadfence();
            g_count = 0u;
        }
    }
}

extern "C" void kernel_launch(void* const* d_in, const int* in_sizes, int n_in,
                              void* d_out, int out_size)
{
    const float* img1 = (const float*)d_in[0];
    const float* img2 = (const float*)d_in[1];

    const int smem_bytes = 2 * HMAP * 8;   // 42,624 B -> 4 CTAs x 256 thr / SM
    cudaFuncSetAttribute(ssim_main, cudaFuncAttributeMaxDynamicSharedMemorySize, smem_bytes);

    dim3 grid(512/TW, 512/TH, 96);
    ssim_main<<<grid, 256, smem_bytes>>>(img1, img2, (float*)d_out);
}